// round 2
// baseline (speedup 1.0000x reference)
#include <cuda_runtime.h>
#include <cuda_bf16.h>
#include <cstdint>

// ===================== problem constants =====================
constexpr int Nn = 8192;
constexpr int Dd = 768;
constexpr int BM = 128;            // Q rows per CTA
constexpr int BN = 128;            // C cols per tile
constexpr int BK = 64;             // K per SMEM chunk (64 bf16 = 128B rows)
constexpr int NKC = Dd / BK;       // 12 K-chunks
constexpr int COLSPLIT = 4;        // grid.y
constexpr int CHUNKS = (Nn / BN) / COLSPLIT;  // 16 col tiles per CTA
constexpr int TOT = CHUNKS * NKC;  // 192 B-chunk iterations
constexpr float INV_T = 20.0f;     // 1/0.05

constexpr int A_BYTES = BM * Dd * 2;                    // 196608
constexpr int B_OFF   = A_BYTES;
constexpr int SMEM_BYTES = A_BYTES + 2 * BN * BK * 2;   // 229376 (<= 227KB opt-in)

// ===================== device scratch =====================
__device__ __align__(16) __nv_bfloat16 g_qn[(size_t)Nn * Dd];
__device__ __align__(16) __nv_bfloat16 g_cn[(size_t)Nn * Dd];
__device__ float g_rows[COLSPLIT][Nn];
__device__ float g_diag[Nn];

// ===================== helpers =====================
__device__ __forceinline__ uint32_t smem_u32(const void* p) {
    uint32_t a;
    asm("{ .reg .u64 t; cvta.to.shared.u64 t, %1; cvt.u32.u64 %0, t; }"
        : "=r"(a) : "l"(p));
    return a;
}

#define SMEM_SWIZZLE_128B(o) ((o) ^ (((o) >> 3) & 0x70))

__device__ __forceinline__ void cp16(uint32_t dst, const void* src) {
    asm volatile("cp.async.cg.shared.global [%0], [%1], 16;" :: "r"(dst), "l"(src));
}
#define CP_COMMIT asm volatile("cp.async.commit_group;" ::: "memory")
#define CP_WAIT1  asm volatile("cp.async.wait_group 1;" ::: "memory")
#define CP_WAIT0  asm volatile("cp.async.wait_group 0;" ::: "memory")

__device__ __forceinline__ void ldm4(uint32_t* r, uint32_t addr) {
    asm volatile("ldmatrix.sync.aligned.m8n8.x4.shared.b16 {%0,%1,%2,%3}, [%4];"
        : "=r"(r[0]), "=r"(r[1]), "=r"(r[2]), "=r"(r[3]) : "r"(addr));
}

__device__ __forceinline__ void mma16816(float* d, const uint32_t* a,
                                         uint32_t b0, uint32_t b1) {
    asm volatile(
        "mma.sync.aligned.m16n8k16.row.col.f32.bf16.bf16.f32 "
        "{%0,%1,%2,%3}, {%4,%5,%6,%7}, {%8,%9}, {%0,%1,%2,%3};"
        : "+f"(d[0]), "+f"(d[1]), "+f"(d[2]), "+f"(d[3])
        : "r"(a[0]), "r"(a[1]), "r"(a[2]), "r"(a[3]), "r"(b0), "r"(b1));
}

// ===================== kernel 1: normalize fp32 -> bf16 =====================
__global__ void __launch_bounds__(256) norm_kernel(const float* __restrict__ q,
                                                   const float* __restrict__ c) {
    int row = blockIdx.x;  // 0..16383
    const float* src;
    __nv_bfloat16* dst;
    if (row < Nn) {
        src = q + (size_t)row * Dd;
        dst = g_qn + (size_t)row * Dd;
    } else {
        src = c + (size_t)(row - Nn) * Dd;
        dst = g_cn + (size_t)(row - Nn) * Dd;
    }
    int tid = threadIdx.x;
    float v[3];
    float ss = 0.f;
#pragma unroll
    for (int i = 0; i < 3; i++) {
        v[i] = src[tid + i * 256];
        ss += v[i] * v[i];
    }
#pragma unroll
    for (int o = 16; o; o >>= 1) ss += __shfl_xor_sync(0xFFFFFFFFu, ss, o);
    __shared__ float sred[8];
    if ((tid & 31) == 0) sred[tid >> 5] = ss;
    __syncthreads();
    float tot = 0.f;
#pragma unroll
    for (int i = 0; i < 8; i++) tot += sred[i];
    float scale = 1.0f / fmaxf(sqrtf(tot), 1e-8f);
#pragma unroll
    for (int i = 0; i < 3; i++) dst[tid + i * 256] = __float2bfloat16(v[i] * scale);
}

// ===================== kernel 2: fused GEMM + exp-rowsum =====================
__global__ void __launch_bounds__(256, 1) simcse_main() {
    extern __shared__ __align__(1024) uint8_t smem[];
    uint8_t* sA = smem;           // 12 chunks of [128 rows][128B] swizzled
    uint8_t* sB = smem + B_OFF;   // 2 buffers of [128 rows][128B] swizzled

    const int tid = threadIdx.x;
    const int lane = tid & 31;
    const int wid = tid >> 5;
    const int warp_m = wid >> 1;   // 0..3
    const int warp_n = wid & 1;    // 0..1
    const int bx = blockIdx.x;     // row block 0..63
    const int by = blockIdx.y;     // col split 0..3
    const int tdiag = (by == (bx >> 4)) ? (bx & 15) : -1;

    const uint32_t sA_u = smem_u32(sA);
    const uint32_t sB_u = smem_u32(sB);

    // ---- stage A: this CTA's 128 Q rows (192KB) via cp.async ----
    {
        const __nv_bfloat16* qbase = g_qn + (size_t)bx * BM * Dd;
#pragma unroll 4
        for (int i = 0; i < 48; i++) {
            int idx = tid + i * 256;        // 0..12287 (16B units)
            int kc = idx >> 10;
            int pos = idx & 1023;
            int r = pos >> 3, c = pos & 7;
            const void* src = qbase + (size_t)r * Dd + kc * BK + c * 8;
            uint32_t dst = sA_u + kc * 16384 +
                           SMEM_SWIZZLE_128B((uint32_t)(r * 128 + c * 16));
            cp16(dst, src);
        }
        CP_COMMIT;
    }

    const __nv_bfloat16* cquad = g_cn + (size_t)by * CHUNKS * BN * Dd;

    auto loadB = [&](int g, int buf) {
        const int t = g / NKC, kc = g % NKC;
        const __nv_bfloat16* cb = cquad + (size_t)t * BN * Dd + kc * BK;
#pragma unroll
        for (int i = 0; i < 4; i++) {
            int pos = tid + i * 256;        // 0..1023
            int r = pos >> 3, c = pos & 7;
            cp16(sB_u + buf * 16384 +
                     SMEM_SWIZZLE_128B((uint32_t)(r * 128 + c * 16)),
                 cb + (size_t)r * Dd + c * 8);
        }
        CP_COMMIT;
    };

    loadB(0, 0);

    // per-lane ldmatrix base offsets (bytes, pre-swizzle)
    const uint32_t aoff0 = (uint32_t)((lane & 15) * 128 + (lane >> 4) * 16) +
                           (uint32_t)warp_m * 4096u;
    const uint32_t boff0 = (uint32_t)(((((lane >> 4) & 1) * 8) + (lane & 7)) * 128 +
                                      ((lane >> 3) & 1) * 16) +
                           (uint32_t)warp_n * 8192u;

    float acc[2][8][4];
#pragma unroll
    for (int mt = 0; mt < 2; mt++)
#pragma unroll
        for (int nt = 0; nt < 8; nt++)
#pragma unroll
            for (int d = 0; d < 4; d++) acc[mt][nt][d] = 0.f;

    float rsum[2][2] = {{0.f, 0.f}, {0.f, 0.f}};  // [mt][row-half]

#pragma unroll 1
    for (int g = 0; g < TOT; g++) {
        const int buf = g & 1;
        if (g + 1 < TOT) {
            loadB(g + 1, buf ^ 1);
            CP_WAIT1;
        } else {
            CP_WAIT0;
        }
        __syncthreads();

        const uint32_t abase = sA_u + (uint32_t)(g % NKC) * 16384u;
        const uint32_t bbase = sB_u + (uint32_t)buf * 16384u;

#pragma unroll
        for (int kk = 0; kk < 4; kk++) {
            uint32_t a[2][4];
#pragma unroll
            for (int mt = 0; mt < 2; mt++)
                ldm4(a[mt], abase + SMEM_SWIZZLE_128B(aoff0 + (uint32_t)(mt * 2048 + kk * 32)));
            uint32_t b[4][4];
#pragma unroll
            for (int ntp = 0; ntp < 4; ntp++)
                ldm4(b[ntp], bbase + SMEM_SWIZZLE_128B(boff0 + (uint32_t)(ntp * 2048 + kk * 32)));
#pragma unroll
            for (int mt = 0; mt < 2; mt++)
#pragma unroll
                for (int ntp = 0; ntp < 4; ntp++) {
                    mma16816(acc[mt][2 * ntp + 0], a[mt], b[ntp][0], b[ntp][1]);
                    mma16816(acc[mt][2 * ntp + 1], a[mt], b[ntp][2], b[ntp][3]);
                }
        }
        __syncthreads();

        if ((g % NKC) == NKC - 1) {
            const int t = g / NKC;
            // epilogue: scale, exp, row partial sums, diagonal capture
#pragma unroll
            for (int mt = 0; mt < 2; mt++)
#pragma unroll
                for (int nt = 0; nt < 8; nt++)
#pragma unroll
                    for (int d = 0; d < 4; d++) {
                        float s = acc[mt][nt][d] * INV_T;
                        if (t == tdiag) {
                            int rl = warp_m * 32 + mt * 16 + (d >> 1) * 8 + (lane >> 2);
                            int cl = warp_n * 64 + nt * 8 + (lane & 3) * 2 + (d & 1);
                            if (rl == cl) g_diag[bx * BM + rl] = s;
                        }
                        rsum[mt][d >> 1] += __expf(s);
                        acc[mt][nt][d] = 0.f;
                    }
        }
    }

    // ---- reduce row sums: quad shuffle, then across the 2 N-warps via SMEM ----
#pragma unroll
    for (int mt = 0; mt < 2; mt++)
#pragma unroll
        for (int h = 0; h < 2; h++) {
            float v = rsum[mt][h];
            v += __shfl_xor_sync(0xFFFFFFFFu, v, 1);
            v += __shfl_xor_sync(0xFFFFFFFFu, v, 2);
            rsum[mt][h] = v;
        }

    float* sred = (float*)smem;  // reuse A region (1KB): [128 rows][2 warp_n]
    __syncthreads();
    if ((lane & 3) == 0) {
#pragma unroll
        for (int mt = 0; mt < 2; mt++)
#pragma unroll
            for (int h = 0; h < 2; h++) {
                int rl = warp_m * 32 + mt * 16 + h * 8 + (lane >> 2);
                sred[rl * 2 + warp_n] = rsum[mt][h];
            }
    }
    __syncthreads();
    if (tid < BM) g_rows[by][bx * BM + tid] = sred[tid * 2] + sred[tid * 2 + 1];
}

// ===================== kernel 3: loss reduction =====================
__global__ void __launch_bounds__(256) loss_kernel(float* __restrict__ out) {
    int tid = threadIdx.x;
    float acc = 0.f;
    for (int i = tid; i < Nn; i += 256) {
        float r = g_rows[0][i] + g_rows[1][i] + g_rows[2][i] + g_rows[3][i];
        acc += logf(r) - g_diag[i];
    }
#pragma unroll
    for (int o = 16; o; o >>= 1) acc += __shfl_xor_sync(0xFFFFFFFFu, acc, o);
    __shared__ float sred[8];
    if ((tid & 31) == 0) sred[tid >> 5] = acc;
    __syncthreads();
    if (tid == 0) {
        float tot = 0.f;
#pragma unroll
        for (int i = 0; i < 8; i++) tot += sred[i];
        out[0] = tot * (1.0f / (float)Nn);
    }
}

// ===================== launch =====================
extern "C" void kernel_launch(void* const* d_in, const int* in_sizes, int n_in,
                              void* d_out, int out_size) {
    const float* q = (const float*)d_in[0];
    const float* c = (const float*)d_in[1];
    float* out = (float*)d_out;

    cudaFuncSetAttribute(simcse_main, cudaFuncAttributeMaxDynamicSharedMemorySize,
                         SMEM_BYTES);

    norm_kernel<<<2 * Nn, 256>>>(q, c);
    simcse_main<<<dim3(Nn / BM, COLSPLIT), 256, SMEM_BYTES>>>();
    loss_kernel<<<1, 256>>>(out);
}

// round 3
// speedup vs baseline: 1.0856x; 1.0856x over previous
#include <cuda_runtime.h>
#include <cuda_bf16.h>
#include <cstdint>

// ===================== problem constants =====================
constexpr int Nn = 8192;
constexpr int Dd = 768;
constexpr int BM = 128;            // Q rows per CTA
constexpr int BN = 128;            // C cols per tile
constexpr int BK = 64;             // K per SMEM chunk (64 bf16 = 128B rows)
constexpr int NKC = Dd / BK;       // 12 K-chunks
constexpr int COLSPLIT = 4;        // grid.y
constexpr int CHUNKS = (Nn / BN) / COLSPLIT;  // 16 col tiles per CTA
constexpr int TOT = CHUNKS * NKC;  // 192 B-chunk iterations
// q rows pre-scaled by 20*log2(e): accumulators are base-2 logits directly
constexpr float QSCALE = 20.0f * 1.4426950408889634f;
constexpr float LN2 = 0.6931471805599453f;

constexpr int A_BYTES = BM * Dd * 2;                    // 196608
constexpr int B_OFF   = A_BYTES;
constexpr int SMEM_BYTES = A_BYTES + 2 * BN * BK * 2;   // 229376

// ===================== device scratch =====================
__device__ __align__(16) __nv_bfloat16 g_qn[(size_t)Nn * Dd];
__device__ __align__(16) __nv_bfloat16 g_cn[(size_t)Nn * Dd];
__device__ float g_rows[COLSPLIT][Nn];
__device__ float g_diag[Nn];   // base-2 scaled diagonal

// ===================== helpers =====================
__device__ __forceinline__ uint32_t smem_u32(const void* p) {
    uint32_t a;
    asm("{ .reg .u64 t; cvta.to.shared.u64 t, %1; cvt.u32.u64 %0, t; }"
        : "=r"(a) : "l"(p));
    return a;
}

#define SMEM_SWIZZLE_128B(o) ((o) ^ (((o) >> 3) & 0x70))

__device__ __forceinline__ void cp16(uint32_t dst, const void* src) {
    asm volatile("cp.async.cg.shared.global [%0], [%1], 16;" :: "r"(dst), "l"(src));
}
#define CP_COMMIT asm volatile("cp.async.commit_group;" ::: "memory")
#define CP_WAIT0  asm volatile("cp.async.wait_group 0;" ::: "memory")

__device__ __forceinline__ void ldm4(uint32_t* r, uint32_t addr) {
    asm volatile("ldmatrix.sync.aligned.m8n8.x4.shared.b16 {%0,%1,%2,%3}, [%4];"
        : "=r"(r[0]), "=r"(r[1]), "=r"(r[2]), "=r"(r[3]) : "r"(addr));
}

__device__ __forceinline__ void mma16816(float* d, const uint32_t* a,
                                         uint32_t b0, uint32_t b1) {
    asm volatile(
        "mma.sync.aligned.m16n8k16.row.col.f32.bf16.bf16.f32 "
        "{%0,%1,%2,%3}, {%4,%5,%6,%7}, {%8,%9}, {%0,%1,%2,%3};"
        : "+f"(d[0]), "+f"(d[1]), "+f"(d[2]), "+f"(d[3])
        : "r"(a[0]), "r"(a[1]), "r"(a[2]), "r"(a[3]), "r"(b0), "r"(b1));
}

__device__ __forceinline__ float ex2f(float x) {
    float y;
    asm("ex2.approx.f32 %0, %1;" : "=f"(y) : "f"(x));
    return y;
}

// ===================== kernel 1: normalize fp32 -> bf16 =====================
__global__ void __launch_bounds__(256) norm_kernel(const float* __restrict__ q,
                                                   const float* __restrict__ c) {
    int row = blockIdx.x;  // 0..16383
    const bool isq = row < Nn;
    const float* src;
    __nv_bfloat16* dst;
    if (isq) {
        src = q + (size_t)row * Dd;
        dst = g_qn + (size_t)row * Dd;
    } else {
        src = c + (size_t)(row - Nn) * Dd;
        dst = g_cn + (size_t)(row - Nn) * Dd;
    }
    int tid = threadIdx.x;
    float v[3];
    float ss = 0.f;
#pragma unroll
    for (int i = 0; i < 3; i++) {
        v[i] = src[tid + i * 256];
        ss += v[i] * v[i];
    }
#pragma unroll
    for (int o = 16; o; o >>= 1) ss += __shfl_xor_sync(0xFFFFFFFFu, ss, o);
    __shared__ float sred[8];
    if ((tid & 31) == 0) sred[tid >> 5] = ss;
    __syncthreads();
    float tot = 0.f;
#pragma unroll
    for (int i = 0; i < 8; i++) tot += sred[i];
    float scale = (isq ? QSCALE : 1.0f) / fmaxf(sqrtf(tot), 1e-8f);
#pragma unroll
    for (int i = 0; i < 3; i++) dst[tid + i * 256] = __float2bfloat16(v[i] * scale);
}

// ===================== kernel 2: fused GEMM + exp2-rowsum =====================
__global__ void __launch_bounds__(128, 1) simcse_main() {
    extern __shared__ __align__(1024) uint8_t smem[];
    uint8_t* sA = smem;           // 12 chunks of [128 rows][128B] swizzled
    uint8_t* sB = smem + B_OFF;   // 2 buffers of [128 rows][128B] swizzled

    const int tid = threadIdx.x;
    const int lane = tid & 31;
    const int wid = tid >> 2 >> 3;            // tid>>5: warp 0..3
    const int warp_m = wid & 1;               // 0..1 (64 rows each)
    const int warp_n = wid >> 1;              // 0..1 (64 cols each)
    const int bx = blockIdx.x;                // row block 0..63
    const int by = blockIdx.y;                // col split 0..3
    const int tdiag = (by == (bx >> 4)) ? (bx & 15) : -1;

    const uint32_t sA_u = smem_u32(sA);
    const uint32_t sB_u = smem_u32(sB);

    // ---- stage A: this CTA's 128 Q rows (192KB) via cp.async ----
    {
        const __nv_bfloat16* qbase = g_qn + (size_t)bx * BM * Dd;
#pragma unroll 4
        for (int i = 0; i < 96; i++) {
            int idx = tid + i * 128;        // 0..12287 (16B units)
            int kc = idx >> 10;
            int pos = idx & 1023;
            int r = pos >> 3, c = pos & 7;
            const void* src = qbase + (size_t)r * Dd + kc * BK + c * 8;
            uint32_t dst = sA_u + kc * 16384 +
                           SMEM_SWIZZLE_128B((uint32_t)(r * 128 + c * 16));
            cp16(dst, src);
        }
    }

    const __nv_bfloat16* cquad = g_cn + (size_t)by * CHUNKS * BN * Dd;

    auto loadB = [&](int g, int buf) {
        const int t = g / NKC, kc = g % NKC;
        const __nv_bfloat16* cb = cquad + (size_t)t * BN * Dd + kc * BK;
#pragma unroll
        for (int i = 0; i < 8; i++) {
            int pos = tid + i * 128;        // 0..1023
            int r = pos >> 3, c = pos & 7;
            cp16(sB_u + buf * 16384 +
                     SMEM_SWIZZLE_128B((uint32_t)(r * 128 + c * 16)),
                 cb + (size_t)r * Dd + c * 8);
        }
        CP_COMMIT;
    };

    loadB(0, 0);  // (A's cp.asyncs join this commit group)

    // per-lane ldmatrix base offsets (bytes, pre-swizzle)
    const uint32_t aoff0 = (uint32_t)((warp_m * 64 + (lane & 15)) * 128 +
                                      (lane >> 4) * 16);
    const uint32_t boff0 = (uint32_t)(((((lane >> 4) & 1) * 8) + (lane & 7)) * 128 +
                                      ((lane >> 3) & 1) * 16) +
                           (uint32_t)warp_n * 8192u;

    float acc[4][8][4];
#pragma unroll
    for (int mt = 0; mt < 4; mt++)
#pragma unroll
        for (int nt = 0; nt < 8; nt++)
#pragma unroll
            for (int d = 0; d < 4; d++) acc[mt][nt][d] = 0.f;

    float rsum[4][2];
#pragma unroll
    for (int mt = 0; mt < 4; mt++) { rsum[mt][0] = 0.f; rsum[mt][1] = 0.f; }

#pragma unroll 1
    for (int g = 0; g < TOT; g++) {
        const int buf = g & 1;
        CP_WAIT0;            // this chunk's B tile (and A on g==0) is resident
        __syncthreads();     // everyone done reading buf^1 (chunk g-1)
        if (g + 1 < TOT) loadB(g + 1, buf ^ 1);

        const uint32_t abase = sA_u + (uint32_t)(g % NKC) * 16384u;
        const uint32_t bbase = sB_u + (uint32_t)buf * 16384u;

        uint32_t a[2][4][4], b[2][4][4];
        // prefetch kk=0 fragments
#pragma unroll
        for (int mt = 0; mt < 4; mt++)
            ldm4(a[0][mt], abase + SMEM_SWIZZLE_128B(aoff0 + (uint32_t)(mt * 2048)));
#pragma unroll
        for (int ntp = 0; ntp < 4; ntp++)
            ldm4(b[0][ntp], bbase + SMEM_SWIZZLE_128B(boff0 + (uint32_t)(ntp * 2048)));

#pragma unroll
        for (int kk = 0; kk < 4; kk++) {
            const int cur = kk & 1, nxt = cur ^ 1;
            if (kk < 3) {
#pragma unroll
                for (int mt = 0; mt < 4; mt++)
                    ldm4(a[nxt][mt], abase + SMEM_SWIZZLE_128B(
                             aoff0 + (uint32_t)(mt * 2048 + (kk + 1) * 32)));
#pragma unroll
                for (int ntp = 0; ntp < 4; ntp++)
                    ldm4(b[nxt][ntp], bbase + SMEM_SWIZZLE_128B(
                             boff0 + (uint32_t)(ntp * 2048 + (kk + 1) * 32)));
            }
#pragma unroll
            for (int mt = 0; mt < 4; mt++)
#pragma unroll
                for (int ntp = 0; ntp < 4; ntp++) {
                    mma16816(acc[mt][2 * ntp + 0], a[cur][mt],
                             b[cur][ntp][0], b[cur][ntp][1]);
                    mma16816(acc[mt][2 * ntp + 1], a[cur][mt],
                             b[cur][ntp][2], b[cur][ntp][3]);
                }
        }

        if ((g % NKC) == NKC - 1) {
            const int t = g / NKC;
            // epilogue: exp2, row partial sums, diagonal capture (base-2 logits)
#pragma unroll
            for (int mt = 0; mt < 4; mt++)
#pragma unroll
                for (int nt = 0; nt < 8; nt++)
#pragma unroll
                    for (int d = 0; d < 4; d++) {
                        float s = acc[mt][nt][d];
                        if (t == tdiag) {
                            int rl = warp_m * 64 + mt * 16 + (d >> 1) * 8 + (lane >> 2);
                            int cl = warp_n * 64 + nt * 8 + (lane & 3) * 2 + (d & 1);
                            if (rl == cl) g_diag[bx * BM + rl] = s;
                        }
                        rsum[mt][d >> 1] += ex2f(s);
                        acc[mt][nt][d] = 0.f;
                    }
        }
    }

    // ---- reduce row sums: quad shuffle, then across the 2 N-warps via SMEM ----
#pragma unroll
    for (int mt = 0; mt < 4; mt++)
#pragma unroll
        for (int h = 0; h < 2; h++) {
            float v = rsum[mt][h];
            v += __shfl_xor_sync(0xFFFFFFFFu, v, 1);
            v += __shfl_xor_sync(0xFFFFFFFFu, v, 2);
            rsum[mt][h] = v;
        }

    float* sred = (float*)smem;  // reuse A region (1KB): [128 rows][2 warp_n]
    __syncthreads();
    if ((lane & 3) == 0) {
#pragma unroll
        for (int mt = 0; mt < 4; mt++)
#pragma unroll
            for (int h = 0; h < 2; h++) {
                int rl = warp_m * 64 + mt * 16 + h * 8 + (lane >> 2);
                sred[rl * 2 + warp_n] = rsum[mt][h];
            }
    }
    __syncthreads();
    if (tid < BM) g_rows[by][bx * BM + tid] = sred[tid * 2] + sred[tid * 2 + 1];
}

// ===================== kernel 3: loss reduction =====================
__global__ void __launch_bounds__(256) loss_kernel(float* __restrict__ out) {
    int tid = threadIdx.x;
    float acc = 0.f;
    for (int i = tid; i < Nn; i += 256) {
        float r = g_rows[0][i] + g_rows[1][i] + g_rows[2][i] + g_rows[3][i];
        acc += logf(r) - g_diag[i] * LN2;   // diag is base-2 scaled
    }
#pragma unroll
    for (int o = 16; o; o >>= 1) acc += __shfl_xor_sync(0xFFFFFFFFu, acc, o);
    __shared__ float sred[8];
    if ((tid & 31) == 0) sred[tid >> 5] = acc;
    __syncthreads();
    if (tid == 0) {
        float tot = 0.f;
#pragma unroll
        for (int i = 0; i < 8; i++) tot += sred[i];
        out[0] = tot * (1.0f / (float)Nn);
    }
}

// ===================== launch =====================
extern "C" void kernel_launch(void* const* d_in, const int* in_sizes, int n_in,
                              void* d_out, int out_size) {
    const float* q = (const float*)d_in[0];
    const float* c = (const float*)d_in[1];
    float* out = (float*)d_out;

    cudaFuncSetAttribute(simcse_main, cudaFuncAttributeMaxDynamicSharedMemorySize,
                         SMEM_BYTES);

    norm_kernel<<<2 * Nn, 256>>>(q, c);
    simcse_main<<<dim3(Nn / BM, COLSPLIT), 128, SMEM_BYTES>>>();
    loss_kernel<<<1, 256>>>(out);
}